// round 1
// baseline (speedup 1.0000x reference)
#include <cuda_runtime.h>

#define NN     4096
#define IND    512
#define HIDD   256
#define NHEAD  2
#define OUTD   40
#define LN_EPS 1e-5f

// Scratch (static device allocations — allowed; no runtime alloc).
__device__ float g_QKV[3][NHEAD][NN][HIDD];     // 24 MB: Q,K,V
__device__ float g_S[NHEAD][NN][NN];            // 134 MB: scores -> probs (in place)
__device__ float g_Xf[NN][NHEAD * HIDD];        // 8 MB: concat attention output
__device__ float g_z[NN][IND];                  // 8 MB: pre-LN activations

#define BM 128
#define BN 128
#define BK 16

// ---------------------------------------------------------------------------
// Kernel 1: Q/K/V projections.  C[4096,256] = h[4096,512] @ W[512,256] + b
// grid: (HIDD/BN=2, NN/BM=32, 6)   z = mat*2 + head
// ---------------------------------------------------------------------------
__global__ __launch_bounds__(256) void qkv_kernel(
    const float* __restrict__ h,
    const float* __restrict__ Wq, const float* __restrict__ bq,
    const float* __restrict__ Wk, const float* __restrict__ bk,
    const float* __restrict__ Wv, const float* __restrict__ bv)
{
    __shared__ float As[BK][BM];
    __shared__ float Bs[BK][BN];

    const int mat  = blockIdx.z >> 1;   // 0=Q 1=K 2=V
    const int head = blockIdx.z & 1;
    const float* W    = (mat == 0 ? Wq : (mat == 1 ? Wk : Wv)) + head * IND * HIDD;
    const float* bias = (mat == 0 ? bq : (mat == 1 ? bk : bv)) + head * HIDD;

    const int m0 = blockIdx.y * BM;
    const int n0 = blockIdx.x * BN;
    const int tid = threadIdx.x;
    const int tx = tid & 15, ty = tid >> 4;

    float acc[8][8] = {};

    for (int k0 = 0; k0 < IND; k0 += BK) {
        #pragma unroll
        for (int l = 0; l < 2; l++) {               // A: 128 rows x 16 k (k-major)
            int lin = tid + l * 256;
            int row = lin >> 2, kv = (lin & 3) * 4;
            float4 v = *(const float4*)&h[(m0 + row) * IND + k0 + kv];
            As[kv + 0][row] = v.x; As[kv + 1][row] = v.y;
            As[kv + 2][row] = v.z; As[kv + 3][row] = v.w;
        }
        #pragma unroll
        for (int l = 0; l < 2; l++) {               // B: 16 k x 128 n (n-major)
            int lin = tid + l * 256;
            int kr = lin >> 5, nv = (lin & 31) * 4;
            *(float4*)&Bs[kr][nv] = *(const float4*)&W[(k0 + kr) * HIDD + n0 + nv];
        }
        __syncthreads();
        #pragma unroll
        for (int kk = 0; kk < BK; kk++) {
            float a[8], b[8];
            *(float4*)&a[0] = *(float4*)&As[kk][ty * 8];
            *(float4*)&a[4] = *(float4*)&As[kk][ty * 8 + 4];
            *(float4*)&b[0] = *(float4*)&Bs[kk][tx * 8];
            *(float4*)&b[4] = *(float4*)&Bs[kk][tx * 8 + 4];
            #pragma unroll
            for (int i = 0; i < 8; i++)
                #pragma unroll
                for (int j = 0; j < 8; j++)
                    acc[i][j] += a[i] * b[j];
        }
        __syncthreads();
    }

    float* C = &g_QKV[mat][head][0][0];
    #pragma unroll
    for (int i = 0; i < 8; i++) {
        int row = m0 + ty * 8 + i;
        #pragma unroll
        for (int j = 0; j < 8; j++) {
            int col = n0 + tx * 8 + j;
            C[row * HIDD + col] = acc[i][j] + bias[col];
        }
    }
}

// ---------------------------------------------------------------------------
// Kernel 2: scores = (Q @ K^T) * adj     (NT GEMM, K=256)
// grid: (32, 32, 2)
// ---------------------------------------------------------------------------
__global__ __launch_bounds__(256) void scores_kernel(const float* __restrict__ adj)
{
    __shared__ float As[BK][BM];
    __shared__ float Bs[BK][BN];

    const int head = blockIdx.z;
    const float* Q  = &g_QKV[0][head][0][0];
    const float* Km = &g_QKV[1][head][0][0];
    const int m0 = blockIdx.y * BM;
    const int n0 = blockIdx.x * BN;
    const int tid = threadIdx.x;
    const int tx = tid & 15, ty = tid >> 4;

    float acc[8][8] = {};

    for (int k0 = 0; k0 < HIDD; k0 += BK) {
        #pragma unroll
        for (int l = 0; l < 2; l++) {               // A: Q rows (k-major)
            int lin = tid + l * 256;
            int row = lin >> 2, kv = (lin & 3) * 4;
            float4 v = *(const float4*)&Q[(m0 + row) * HIDD + k0 + kv];
            As[kv + 0][row] = v.x; As[kv + 1][row] = v.y;
            As[kv + 2][row] = v.z; As[kv + 3][row] = v.w;
        }
        #pragma unroll
        for (int l = 0; l < 2; l++) {               // B: K rows (k-major, NT)
            int lin = tid + l * 256;
            int row = lin >> 2, kv = (lin & 3) * 4;
            float4 v = *(const float4*)&Km[(n0 + row) * HIDD + k0 + kv];
            Bs[kv + 0][row] = v.x; Bs[kv + 1][row] = v.y;
            Bs[kv + 2][row] = v.z; Bs[kv + 3][row] = v.w;
        }
        __syncthreads();
        #pragma unroll
        for (int kk = 0; kk < BK; kk++) {
            float a[8], b[8];
            *(float4*)&a[0] = *(float4*)&As[kk][ty * 8];
            *(float4*)&a[4] = *(float4*)&As[kk][ty * 8 + 4];
            *(float4*)&b[0] = *(float4*)&Bs[kk][tx * 8];
            *(float4*)&b[4] = *(float4*)&Bs[kk][tx * 8 + 4];
            #pragma unroll
            for (int i = 0; i < 8; i++)
                #pragma unroll
                for (int j = 0; j < 8; j++)
                    acc[i][j] += a[i] * b[j];
        }
        __syncthreads();
    }

    #pragma unroll
    for (int i = 0; i < 8; i++) {
        int row = m0 + ty * 8 + i;
        const float* arow = adj + ((size_t)head * NN + row) * NN;
        float* srow = &g_S[head][row][0];
        #pragma unroll
        for (int jv = 0; jv < 2; jv++) {
            int col = n0 + tx * 8 + jv * 4;
            float4 av = *(const float4*)&arow[col];
            float4 s;
            s.x = acc[i][jv * 4 + 0] * av.x;
            s.y = acc[i][jv * 4 + 1] * av.y;
            s.z = acc[i][jv * 4 + 2] * av.z;
            s.w = acc[i][jv * 4 + 3] * av.w;
            *(float4*)&srow[col] = s;
        }
    }
}

// ---------------------------------------------------------------------------
// Kernel 3: row softmax in place on g_S.  grid: (4096, 2), 256 threads.
// Row lives in smem, single gmem read + single write.
// ---------------------------------------------------------------------------
__global__ __launch_bounds__(256) void softmax_kernel()
{
    __shared__ float rowbuf[NN];
    __shared__ float red[256];

    const int head = blockIdx.y;
    const int row  = blockIdx.x;
    float* S = &g_S[head][row][0];
    const int tid = threadIdx.x;

    float4* rb4 = (float4*)rowbuf;
    float4* s4  = (float4*)S;

    float lmax = -1e30f;
    for (int j = tid; j < NN / 4; j += 256) {
        float4 v = s4[j];
        rb4[j] = v;
        lmax = fmaxf(fmaxf(lmax, v.x), fmaxf(v.y, fmaxf(v.z, v.w)));
    }
    red[tid] = lmax;
    __syncthreads();
    for (int s = 128; s > 0; s >>= 1) {
        if (tid < s) red[tid] = fmaxf(red[tid], red[tid + s]);
        __syncthreads();
    }
    const float mx = red[0];
    __syncthreads();

    float lsum = 0.f;
    for (int j = tid; j < NN / 4; j += 256) {
        float4 v = rb4[j];
        v.x = __expf(v.x - mx); v.y = __expf(v.y - mx);
        v.z = __expf(v.z - mx); v.w = __expf(v.w - mx);
        rb4[j] = v;
        lsum += (v.x + v.y) + (v.z + v.w);
    }
    red[tid] = lsum;
    __syncthreads();
    for (int s = 128; s > 0; s >>= 1) {
        if (tid < s) red[tid] += red[tid + s];
        __syncthreads();
    }
    const float inv = 1.0f / red[0];

    for (int j = tid; j < NN / 4; j += 256) {
        float4 v = rb4[j];
        v.x *= inv; v.y *= inv; v.z *= inv; v.w *= inv;
        s4[j] = v;
    }
}

// ---------------------------------------------------------------------------
// Kernel 4: X = P @ V  (NN GEMM, K=4096) -> write concat layout g_Xf
// grid: (2, 32, 2)
// ---------------------------------------------------------------------------
__global__ __launch_bounds__(256) void attnv_kernel()
{
    __shared__ float As[BK][BM];
    __shared__ float Bs[BK][BN];

    const int head = blockIdx.z;
    const float* P = &g_S[head][0][0];
    const float* V = &g_QKV[2][head][0][0];
    const int m0 = blockIdx.y * BM;
    const int n0 = blockIdx.x * BN;
    const int tid = threadIdx.x;
    const int tx = tid & 15, ty = tid >> 4;

    float acc[8][8] = {};

    for (int k0 = 0; k0 < NN; k0 += BK) {
        #pragma unroll
        for (int l = 0; l < 2; l++) {               // A: P rows (k-major, lda=NN)
            int lin = tid + l * 256;
            int row = lin >> 2, kv = (lin & 3) * 4;
            float4 v = *(const float4*)&P[(size_t)(m0 + row) * NN + k0 + kv];
            As[kv + 0][row] = v.x; As[kv + 1][row] = v.y;
            As[kv + 2][row] = v.z; As[kv + 3][row] = v.w;
        }
        #pragma unroll
        for (int l = 0; l < 2; l++) {               // B: V (n-major, ldb=HIDD)
            int lin = tid + l * 256;
            int kr = lin >> 5, nv = (lin & 31) * 4;
            *(float4*)&Bs[kr][nv] = *(const float4*)&V[(k0 + kr) * HIDD + n0 + nv];
        }
        __syncthreads();
        #pragma unroll
        for (int kk = 0; kk < BK; kk++) {
            float a[8], b[8];
            *(float4*)&a[0] = *(float4*)&As[kk][ty * 8];
            *(float4*)&a[4] = *(float4*)&As[kk][ty * 8 + 4];
            *(float4*)&b[0] = *(float4*)&Bs[kk][tx * 8];
            *(float4*)&b[4] = *(float4*)&Bs[kk][tx * 8 + 4];
            #pragma unroll
            for (int i = 0; i < 8; i++)
                #pragma unroll
                for (int j = 0; j < 8; j++)
                    acc[i][j] += a[i] * b[j];
        }
        __syncthreads();
    }

    #pragma unroll
    for (int i = 0; i < 8; i++) {
        int row = m0 + ty * 8 + i;
        #pragma unroll
        for (int j = 0; j < 8; j++) {
            int col = n0 + tx * 8 + j;
            g_Xf[row][head * HIDD + col] = acc[i][j];
        }
    }
}

// ---------------------------------------------------------------------------
// Kernel 5: z = Xf @ Wo + bo   (NN GEMM, 4096x512x512)   grid: (4, 32)
// ---------------------------------------------------------------------------
__global__ __launch_bounds__(256) void z_kernel(
    const float* __restrict__ Wo, const float* __restrict__ bo)
{
    __shared__ float As[BK][BM];
    __shared__ float Bs[BK][BN];

    const int m0 = blockIdx.y * BM;
    const int n0 = blockIdx.x * BN;
    const int tid = threadIdx.x;
    const int tx = tid & 15, ty = tid >> 4;
    const float* A = &g_Xf[0][0];

    float acc[8][8] = {};

    for (int k0 = 0; k0 < IND; k0 += BK) {
        #pragma unroll
        for (int l = 0; l < 2; l++) {
            int lin = tid + l * 256;
            int row = lin >> 2, kv = (lin & 3) * 4;
            float4 v = *(const float4*)&A[(m0 + row) * IND + k0 + kv];
            As[kv + 0][row] = v.x; As[kv + 1][row] = v.y;
            As[kv + 2][row] = v.z; As[kv + 3][row] = v.w;
        }
        #pragma unroll
        for (int l = 0; l < 2; l++) {
            int lin = tid + l * 256;
            int kr = lin >> 5, nv = (lin & 31) * 4;
            *(float4*)&Bs[kr][nv] = *(const float4*)&Wo[(k0 + kr) * IND + n0 + nv];
        }
        __syncthreads();
        #pragma unroll
        for (int kk = 0; kk < BK; kk++) {
            float a[8], b[8];
            *(float4*)&a[0] = *(float4*)&As[kk][ty * 8];
            *(float4*)&a[4] = *(float4*)&As[kk][ty * 8 + 4];
            *(float4*)&b[0] = *(float4*)&Bs[kk][tx * 8];
            *(float4*)&b[4] = *(float4*)&Bs[kk][tx * 8 + 4];
            #pragma unroll
            for (int i = 0; i < 8; i++)
                #pragma unroll
                for (int j = 0; j < 8; j++)
                    acc[i][j] += a[i] * b[j];
        }
        __syncthreads();
    }

    #pragma unroll
    for (int i = 0; i < 8; i++) {
        int row = m0 + ty * 8 + i;
        #pragma unroll
        for (int j = 0; j < 8; j++) {
            int col = n0 + tx * 8 + j;
            g_z[row][col] = acc[i][j] + bo[col];
        }
    }
}

// ---------------------------------------------------------------------------
// Kernel 6: per-row LayerNorm -> M @ Wp + bp -> softmax(40).  grid: 4096
// ---------------------------------------------------------------------------
__global__ __launch_bounds__(128) void lnproj_kernel(
    const float* __restrict__ gamma, const float* __restrict__ beta,
    const float* __restrict__ Wp, const float* __restrict__ bp,
    float* __restrict__ out)
{
    __shared__ float Ms[IND];
    __shared__ float red[128];
    __shared__ float lg[OUTD];

    const int row = blockIdx.x;
    const int tid = threadIdx.x;
    const float* z = &g_z[row][0];

    float s = 0.f, ss = 0.f;
    for (int j = tid; j < IND; j += 128) {
        float x = z[j];
        Ms[j] = x;
        s += x;
        ss += x * x;
    }
    red[tid] = s;
    __syncthreads();
    for (int k = 64; k > 0; k >>= 1) {
        if (tid < k) red[tid] += red[tid + k];
        __syncthreads();
    }
    const float mu = red[0] * (1.0f / IND);
    __syncthreads();
    red[tid] = ss;
    __syncthreads();
    for (int k = 64; k > 0; k >>= 1) {
        if (tid < k) red[tid] += red[tid + k];
        __syncthreads();
    }
    const float var  = red[0] * (1.0f / IND) - mu * mu;
    const float rstd = rsqrtf(var + LN_EPS);

    for (int j = tid; j < IND; j += 128)
        Ms[j] = (Ms[j] - mu) * rstd * gamma[j] + beta[j];
    __syncthreads();

    if (tid < OUTD) {
        float acc = bp[tid];
        #pragma unroll 8
        for (int j = 0; j < IND; j++)
            acc += Ms[j] * Wp[j * OUTD + tid];
        lg[tid] = acc;
    }
    __syncthreads();

    if (tid < OUTD) {
        float mx = -1e30f;
        #pragma unroll
        for (int o = 0; o < OUTD; o++) mx = fmaxf(mx, lg[o]);
        float sum = 0.f;
        #pragma unroll
        for (int o = 0; o < OUTD; o++) sum += __expf(lg[o] - mx);
        out[row * OUTD + tid] = __expf(lg[tid] - mx) / sum;
    }
}

// ---------------------------------------------------------------------------
extern "C" void kernel_launch(void* const* d_in, const int* in_sizes, int n_in,
                              void* d_out, int out_size)
{
    const float* adj   = (const float*)d_in[0];
    const float* h     = (const float*)d_in[1];
    const float* Wq    = (const float*)d_in[2];
    const float* bq    = (const float*)d_in[3];
    const float* Wk    = (const float*)d_in[4];
    const float* bk    = (const float*)d_in[5];
    const float* Wv    = (const float*)d_in[6];
    const float* bv    = (const float*)d_in[7];
    const float* Wo    = (const float*)d_in[8];
    const float* bo    = (const float*)d_in[9];
    const float* gamma = (const float*)d_in[10];
    const float* beta  = (const float*)d_in[11];
    const float* Wp    = (const float*)d_in[12];
    const float* bp    = (const float*)d_in[13];
    float* out = (float*)d_out;

    qkv_kernel<<<dim3(HIDD / BN, NN / BM, 6), 256>>>(h, Wq, bq, Wk, bk, Wv, bv);
    scores_kernel<<<dim3(NN / BN, NN / BM, NHEAD), 256>>>(adj);
    softmax_kernel<<<dim3(NN, NHEAD), 256>>>();
    attnv_kernel<<<dim3(HIDD / BN, NN / BM, NHEAD), 256>>>();
    z_kernel<<<dim3(IND / BN, NN / BM), 256>>>(Wo, bo);
    lnproj_kernel<<<NN, 128>>>(gamma, beta, Wp, bp, out);
}